// round 6
// baseline (speedup 1.0000x reference)
#include <cuda_runtime.h>
#include <cstdint>

typedef unsigned long long ull;

#define TOKENS 4096
#define PDIM   1024
#define PHALF  512
#define NKEYS  512
#define PTOPK  32

// ---------------- scratch (static device allocations; no cudaMalloc) ----------------
__device__ float g_query[TOKENS * PDIM];
__device__ float g_gate [TOKENS * PDIM];
__device__ float g_s1   [TOKENS * NKEYS];
__device__ float g_s2   [TOKENS * NKEYS];
__device__ float g_mid  [TOKENS * PDIM];
__device__ int   g_tidx [TOKENS * PTOPK];
__device__ float g_tw   [TOKENS * PTOPK];

// ---------------- f32x2 packed-FMA helpers (Blackwell FFMA2 path) ----------------
__device__ __forceinline__ void fma2(ull &acc, ull a, ull b) {
    asm("fma.rn.f32x2 %0, %1, %2, %3;" : "=l"(acc) : "l"(a), "l"(b), "l"(acc));
}
__device__ __forceinline__ float2 upk2(ull v) {
    float2 r; asm("mov.b64 {%0, %1}, %2;" : "=f"(r.x), "=f"(r.y) : "l"(v)); return r;
}

// ---------------- fused TN SGEMM, double-buffered smem, dup'd-B layout ----------------
// C[M,N] = A[M,K] * B[N,K]^T (+bias, optional silu).
// Grid.x split: blocks [0,nx0) use {B0,bias0,C0,act0}; rest use {B1,...} with
// A column-offset aoff1 (fuses two GEMMs sharing A into one launch).
//
// Issue-mix optimization: B is stored DUPLICATED in smem (each value twice),
// so an LDS.128 yields two f32x2 broadcast pairs directly. A operand pairs are
// two consecutive m-rows (contiguous in k-major As). Zero MOVs in the inner
// loop: 32 FFMA2 + 6 LDS.128 per k-step.
#define BM 128
#define BN 128
#define BK 16
#define BN2 260   // 2*BN + 4; ≡4 mod 8 -> conflict-floor stores, 16B-aligned rows

__global__ __launch_bounds__(256, 2)
void gemm_tn(const float* __restrict__ A,
             const float* __restrict__ B0, const float* __restrict__ B1,
             const float* __restrict__ bias0, const float* __restrict__ bias1,
             float* __restrict__ C0, float* __restrict__ C1,
             int K, int lda, int ldb, int ldc,
             int nx0, int aoff1, int act0, int act1)
{
    __shared__ __align__(16) float As[2][BK][BM + 4];
    __shared__ __align__(16) float Bs[2][BK][BN2];

    const bool sec = (int)blockIdx.x >= nx0;
    const float* B    = sec ? B1    : B0;
    const float* bias = sec ? bias1 : bias0;
    float*       C    = sec ? C1    : C0;
    const int    act  = sec ? act1  : act0;
    const int    bn   = (sec ? (int)blockIdx.x - nx0 : (int)blockIdx.x) * BN;
    const float* Ab   = A + (sec ? aoff1 : 0);

    const int tid = threadIdx.x;
    const int bm  = blockIdx.y * BM;
    const int lr  = tid >> 2;          // 0..63
    const int lc  = (tid & 3) * 4;     // 0,4,8,12 (k-direction)
    const int tx  = tid & 15;          // col group (8 cols)
    const int ty  = tid >> 4;          // row group (8 rows)

    const float* Ap0 = Ab + (size_t)(bm + lr) * lda + lc;
    const float* Ap1 = Ap0 + (size_t)64 * lda;
    const float* Bp0 = B + (size_t)(bn + lr) * ldb + lc;
    const float* Bp1 = Bp0 + (size_t)64 * ldb;

    float4 av0 = *(const float4*)Ap0;
    float4 av1 = *(const float4*)Ap1;
    float4 bv0 = *(const float4*)Bp0;
    float4 bv1 = *(const float4*)Bp1;

    // acc[r][c]: rows (ty*8+2r, ty*8+2r+1) packed in f32x2, col bn+tx*8+c
    ull acc[4][8];
    #pragma unroll
    for (int r = 0; r < 4; r++)
        #pragma unroll
        for (int c = 0; c < 8; c++) acc[r][c] = 0ull;

    // helpers to fill a stage
    #define FILL_STAGE(S)                                                        \
        do {                                                                     \
            As[S][lc + 0][lr]      = av0.x; As[S][lc + 1][lr]      = av0.y;      \
            As[S][lc + 2][lr]      = av0.z; As[S][lc + 3][lr]      = av0.w;      \
            As[S][lc + 0][lr + 64] = av1.x; As[S][lc + 1][lr + 64] = av1.y;      \
            As[S][lc + 2][lr + 64] = av1.z; As[S][lc + 3][lr + 64] = av1.w;      \
            *(float2*)&Bs[S][lc + 0][2*lr]      = make_float2(bv0.x, bv0.x);     \
            *(float2*)&Bs[S][lc + 1][2*lr]      = make_float2(bv0.y, bv0.y);     \
            *(float2*)&Bs[S][lc + 2][2*lr]      = make_float2(bv0.z, bv0.z);     \
            *(float2*)&Bs[S][lc + 3][2*lr]      = make_float2(bv0.w, bv0.w);     \
            *(float2*)&Bs[S][lc + 0][2*lr+128]  = make_float2(bv1.x, bv1.x);     \
            *(float2*)&Bs[S][lc + 1][2*lr+128]  = make_float2(bv1.y, bv1.y);     \
            *(float2*)&Bs[S][lc + 2][2*lr+128]  = make_float2(bv1.z, bv1.z);     \
            *(float2*)&Bs[S][lc + 3][2*lr+128]  = make_float2(bv1.w, bv1.w);     \
        } while (0)

    FILL_STAGE(0);
    __syncthreads();

    int st = 0;
    for (int k0 = 0; k0 < K; k0 += BK) {
        const bool more = (k0 + BK) < K;
        if (more) {  // prefetch next tile into registers
            av0 = *(const float4*)(Ap0 + k0 + BK);
            av1 = *(const float4*)(Ap1 + k0 + BK);
            bv0 = *(const float4*)(Bp0 + k0 + BK);
            bv1 = *(const float4*)(Bp1 + k0 + BK);
        }

        #pragma unroll
        for (int k = 0; k < BK; k++) {
            ulonglong2 aq0 = *(const ulonglong2*)&As[st][k][ty * 8];
            ulonglong2 aq1 = *(const ulonglong2*)&As[st][k][ty * 8 + 4];
            ull ap[4] = { aq0.x, aq0.y, aq1.x, aq1.y };
            const ulonglong2* bp = (const ulonglong2*)&Bs[st][k][tx * 16];
            ulonglong2 bq0 = bp[0], bq1 = bp[1], bq2 = bp[2], bq3 = bp[3];
            ull bd[8] = { bq0.x, bq0.y, bq1.x, bq1.y, bq2.x, bq2.y, bq3.x, bq3.y };
            #pragma unroll
            for (int r = 0; r < 4; r++)
                #pragma unroll
                for (int c = 0; c < 8; c++) fma2(acc[r][c], ap[r], bd[c]);
        }

        if (more) FILL_STAGE(st ^ 1);
        __syncthreads();
        st ^= 1;
    }
    #undef FILL_STAGE

    // epilogue: unpack row pairs, add bias, optional silu, vector stores
    const int col0 = bn + tx * 8;
    float bb[8];
    #pragma unroll
    for (int c = 0; c < 8; c++) bb[c] = bias ? bias[col0 + c] : 0.f;

    #pragma unroll
    for (int r = 0; r < 4; r++) {
        float lo[8], hi[8];
        #pragma unroll
        for (int c = 0; c < 8; c++) {
            float2 v = upk2(acc[r][c]);
            lo[c] = v.x + bb[c];
            hi[c] = v.y + bb[c];
            if (act) {
                lo[c] = lo[c] * (1.f / (1.f + __expf(-lo[c])));
                hi[c] = hi[c] * (1.f / (1.f + __expf(-hi[c])));
            }
        }
        float* r0 = &C[(size_t)(bm + ty * 8 + 2 * r)     * ldc + col0];
        float* r1 = &C[(size_t)(bm + ty * 8 + 2 * r + 1) * ldc + col0];
        *(float4*)(r0)     = make_float4(lo[0], lo[1], lo[2], lo[3]);
        *(float4*)(r0 + 4) = make_float4(lo[4], lo[5], lo[6], lo[7]);
        *(float4*)(r1)     = make_float4(hi[0], hi[1], hi[2], hi[3]);
        *(float4*)(r1 + 4) = make_float4(hi[4], hi[5], hi[6], hi[7]);
    }
}

// ---------------- top-k (warp per token, registers only) ----------------
__device__ __forceinline__ unsigned ford(float v) {
    unsigned u = __float_as_uint(v);
    return (u & 0x80000000u) ? ~u : (u | 0x80000000u);
}
__device__ __forceinline__ float funord(unsigned k) {
    unsigned u = (k & 0x80000000u) ? (k ^ 0x80000000u) : ~k;
    return __uint_as_float(u);
}
__device__ __forceinline__ ull mkkey(float v, int idx) {
    return ((ull)ford(v) << 32) | (unsigned)(0xFFFFFFFFu - (unsigned)idx);
}

// stage 1/2: top-32 of 512; idx = j*32 + lane (owner = idx&31, slot = idx>>5)
__device__ __forceinline__ void select32_512(ull* kk, int lane, float &ov, int &oi) {
    for (int it = 0; it < PTOPK; ++it) {
        ull best = kk[0];
        #pragma unroll
        for (int j = 1; j < 16; j++) if (kk[j] > best) best = kk[j];
        #pragma unroll
        for (int o = 16; o > 0; o >>= 1) {
            ull t = __shfl_xor_sync(0xFFFFFFFFu, best, o);
            if (t > best) best = t;
        }
        int idx = (int)(0xFFFFFFFFu - (unsigned)best);
        if (lane == it) { ov = funord((unsigned)(best >> 32)); oi = idx; }
        int owner = idx & 31;
        int slot  = idx >> 5;
        if (lane == owner) {
            #pragma unroll
            for (int j = 0; j < 16; j++) if (j == slot) kk[j] = 0ull;
        }
    }
}

__global__ void topk_kernel() {
    const int gw   = (blockIdx.x * blockDim.x + threadIdx.x) >> 5;  // token
    const int lane = threadIdx.x & 31;
    const float* s1 = g_s1 + (size_t)gw * NKEYS;
    const float* s2 = g_s2 + (size_t)gw * NKEYS;

    float s1v = 0.f, s2v = 0.f, selv = 0.f;
    int   s1i = 0,   s2i = 0,   selp = 0;

    {
        ull kk[16];
        #pragma unroll
        for (int j = 0; j < 16; j++) { int idx = j * 32 + lane; kk[j] = mkkey(s1[idx], idx); }
        select32_512(kk, lane, s1v, s1i);
    }
    {
        ull kk[16];
        #pragma unroll
        for (int j = 0; j < 16; j++) { int idx = j * 32 + lane; kk[j] = mkkey(s2[idx], idx); }
        select32_512(kk, lane, s2v, s2i);
    }

    // Stage 3: top-32 of the 32x32 sum grid via sorted-merge pointer walk.
    // s1v (lane = rank i) and s2v (lane = rank j) are rank-sorted descending
    // with exact jax tie-breaking; each lane's candidates s1v + s2v[p]
    // (position lane*32+p) are sorted. Warp float-max + ballot; lowest set
    // lane = lowest position = jax tie-break.
    {
        int p = 0;
        float v = s1v + __shfl_sync(0xFFFFFFFFu, s2v, 0);
        for (int it = 0; it < PTOPK; ++it) {
            float bv = v;
            #pragma unroll
            for (int o = 16; o > 0; o >>= 1)
                bv = fmaxf(bv, __shfl_xor_sync(0xFFFFFFFFu, bv, o));
            unsigned m = __ballot_sync(0xFFFFFFFFu, v == bv);
            int wl = __ffs(m) - 1;
            int wp = __shfl_sync(0xFFFFFFFFu, p, wl);
            if (lane == it) { selv = bv; selp = wl * 32 + wp; }
            bool won = (lane == wl);
            p += won;
            float ns2 = __shfl_sync(0xFFFFFFFFu, s2v, p < 32 ? p : 31);
            if (won) v = (p < 32) ? (s1v + ns2) : -3.4e38f;
        }
    }

    // softmax(scores / sqrt(1024)); lane 0 holds the max
    float mx = __shfl_sync(0xFFFFFFFFu, selv, 0);
    float e = __expf((selv - mx) * 0.03125f);
    float s = e;
    #pragma unroll
    for (int o = 16; o > 0; o >>= 1) s += __shfl_xor_sync(0xFFFFFFFFu, s, o);
    float w = e / s;

    int i1 = __shfl_sync(0xFFFFFFFFu, s1i, selp >> 5);
    int i2 = __shfl_sync(0xFFFFFFFFu, s2i, selp & 31);
    g_tidx[gw * PTOPK + lane] = i1 * NKEYS + i2;
    g_tw  [gw * PTOPK + lane] = w;
}

// ---------------- gather + weighted sum + gate (HBM-bound, ~80% of spec) ----------
__global__ void gather_kernel(const float* __restrict__ values) {
    const int token = blockIdx.x;
    const int tid   = threadIdx.x;
    __shared__ int   sidx[PTOPK];
    __shared__ float sw  [PTOPK];
    if (tid < PTOPK) {
        sidx[tid] = g_tidx[token * PTOPK + tid];
        sw  [tid] = g_tw  [token * PTOPK + tid];
    }
    __syncthreads();

    float4 acc = make_float4(0.f, 0.f, 0.f, 0.f);
    #pragma unroll 8
    for (int k = 0; k < PTOPK; k++) {
        const float4* row = (const float4*)(values + (size_t)sidx[k] * PDIM);
        float4 v = __ldg(row + tid);
        float wk = sw[k];
        acc.x += wk * v.x; acc.y += wk * v.y; acc.z += wk * v.z; acc.w += wk * v.w;
    }
    float4 g = ((const float4*)(g_gate + (size_t)token * PDIM))[tid];
    acc.x *= g.x; acc.y *= g.y; acc.z *= g.z; acc.w *= g.w;
    ((float4*)(g_mid + (size_t)token * PDIM))[tid] = acc;
}

// ---------------- launch ----------------
extern "C" void kernel_launch(void* const* d_in, const int* in_sizes, int n_in,
                              void* d_out, int out_size) {
    (void)in_sizes; (void)n_in; (void)out_size;
    const float* x      = (const float*)d_in[0];
    const float* ke1    = (const float*)d_in[1];
    const float* ke2    = (const float*)d_in[2];
    const float* values = (const float*)d_in[3];
    const float* Wq     = (const float*)d_in[4];
    const float* bq     = (const float*)d_in[5];
    const float* Wg     = (const float*)d_in[6];
    const float* bg     = (const float*)d_in[7];
    const float* Wo     = (const float*)d_in[8];
    const float* bo     = (const float*)d_in[9];
    float* out = (float*)d_out;

    float *q, *gt, *s1, *s2, *mid;
    cudaGetSymbolAddress((void**)&q,   g_query);
    cudaGetSymbolAddress((void**)&gt,  g_gate);
    cudaGetSymbolAddress((void**)&s1,  g_s1);
    cudaGetSymbolAddress((void**)&s2,  g_s2);
    cudaGetSymbolAddress((void**)&mid, g_mid);

    dim3 blk(256);
    // fused: query = x@Wq^T + bq  ||  gate = silu(x@Wg^T + bg)   (grid 512)
    gemm_tn<<<dim3(16, TOKENS / BM), blk>>>(x, Wq, Wg, bq, bg, q, gt,
                                            PDIM, PDIM, PDIM, PDIM,
                                            /*nx0=*/8, /*aoff1=*/0, 0, 1);
    // fused: s1 = q[:, :512]@ke1^T  ||  s2 = q[:, 512:]@ke2^T    (grid 256)
    gemm_tn<<<dim3(8, TOKENS / BM), blk>>>(q, ke1, ke2, nullptr, nullptr, s1, s2,
                                           PHALF, PDIM, PHALF, NKEYS,
                                           /*nx0=*/4, /*aoff1=*/PHALF, 0, 0);
    // two-stage top-k + softmax weights (warp per token)
    topk_kernel<<<TOKENS / 8, 256>>>();
    // weighted gather of values rows, times gate
    gather_kernel<<<TOKENS, 256>>>(values);
    // out = mid@Wo^T + bo                                        (grid 256)
    gemm_tn<<<dim3(8, TOKENS / BM), blk>>>(mid, Wo, Wo, bo, bo, out, out,
                                           PDIM, PDIM, PDIM, PDIM,
                                           /*nx0=*/8, /*aoff1=*/0, 0, 0);
}

// round 7
// speedup vs baseline: 2.0444x; 2.0444x over previous
#include <cuda_runtime.h>
#include <cstdint>

typedef unsigned long long ull;

#define TOKENS 4096
#define PDIM   1024
#define PHALF  512
#define NKEYS  512
#define PTOPK  32

// ---------------- scratch (static device allocations; no cudaMalloc) ----------------
__device__ float g_query[TOKENS * PDIM];
__device__ float g_gate [TOKENS * PDIM];
__device__ float g_s1   [TOKENS * NKEYS];
__device__ float g_s2   [TOKENS * NKEYS];
__device__ float g_mid  [TOKENS * PDIM];
__device__ int   g_tidx [TOKENS * PTOPK];
__device__ float g_tw   [TOKENS * PTOPK];

// ---------------- f32x2 packed-FMA helpers (Blackwell FFMA2 path) ----------------
__device__ __forceinline__ void fma2(ull &acc, ull a, ull b) {
    asm("fma.rn.f32x2 %0, %1, %2, %3;" : "=l"(acc) : "l"(a), "l"(b), "l"(acc));
}
__device__ __forceinline__ float2 upk2(ull v) {
    float2 r; asm("mov.b64 {%0, %1}, %2;" : "=f"(r.x), "=f"(r.y) : "l"(v)); return r;
}

// ---------------- fused TN SGEMM, double-buffered, duplicated-A smem ----------------
// C[M,N] = A[M,K] * B[N,K]^T (+bias, optional silu).
// Grid.x split: blocks [0,nx0) use {B0,bias0,C0,act0}; rest use {B1,...} with
// A column-offset aoff1 (fuses two GEMMs sharing A into one launch).
//
// Issue-mix: A is stored DUPLICATED in smem (As2[k][2m]=As2[k][2m+1]=a), so a
// thread's 8 broadcast f32x2 operands are 16 contiguous words = 4 LDS.128 with
// only 2 distinct addresses per warp (ty in {0,1}) -> pure broadcast, no
// conflicts, no MOVs. B stays non-duplicated; contiguous col pairs are the
// f32x2 pair operands (2 LDS.128). Inner loop: 32 FFMA2 + 6 LDS, zero MOV.
#define BM 128
#define BN 128
#define BK 16
#define AROW 256   // 2*BM, exact (static smem budget = 48KB)
#define BROW 128   // BN, exact

__global__ __launch_bounds__(256, 2)
void gemm_tn(const float* __restrict__ A,
             const float* __restrict__ B0, const float* __restrict__ B1,
             const float* __restrict__ bias0, const float* __restrict__ bias1,
             float* __restrict__ C0, float* __restrict__ C1,
             int K, int lda, int ldb, int ldc,
             int nx0, int aoff1, int act0, int act1)
{
    __shared__ __align__(16) float As2[2][BK][AROW];
    __shared__ __align__(16) float Bs [2][BK][BROW];

    const bool sec = (int)blockIdx.x >= nx0;
    const float* B    = sec ? B1    : B0;
    const float* bias = sec ? bias1 : bias0;
    float*       C    = sec ? C1    : C0;
    const int    act  = sec ? act1  : act0;
    const int    bn   = (sec ? (int)blockIdx.x - nx0 : (int)blockIdx.x) * BN;
    const float* Ab   = A + (sec ? aoff1 : 0);

    const int tid = threadIdx.x;
    const int bm  = blockIdx.y * BM;
    const int lr  = tid >> 2;          // 0..63
    const int lc  = (tid & 3) * 4;     // 0,4,8,12 (k-direction)
    const int tx  = tid & 15;          // col group (8 cols)
    const int ty  = tid >> 4;          // row group (8 rows)

    const float* Ap0 = Ab + (size_t)(bm + lr) * lda + lc;
    const float* Ap1 = Ap0 + (size_t)64 * lda;
    const float* Bp0 = B + (size_t)(bn + lr) * ldb + lc;
    const float* Bp1 = Bp0 + (size_t)64 * ldb;

    float4 av0 = *(const float4*)Ap0;
    float4 av1 = *(const float4*)Ap1;
    float4 bv0 = *(const float4*)Bp0;
    float4 bv1 = *(const float4*)Bp1;

    // acc[r][c]: row bm+ty*8+r, cols (bn+tx*8+2c, +2c+1) packed in f32x2
    ull acc[8][4];
    #pragma unroll
    for (int r = 0; r < 8; r++)
        #pragma unroll
        for (int c = 0; c < 4; c++) acc[r][c] = 0ull;

    #define FILL_STAGE(S)                                                       \
        do {                                                                    \
            *(float2*)&As2[S][lc + 0][2*lr]       = make_float2(av0.x, av0.x);  \
            *(float2*)&As2[S][lc + 1][2*lr]       = make_float2(av0.y, av0.y);  \
            *(float2*)&As2[S][lc + 2][2*lr]       = make_float2(av0.z, av0.z);  \
            *(float2*)&As2[S][lc + 3][2*lr]       = make_float2(av0.w, av0.w);  \
            *(float2*)&As2[S][lc + 0][2*lr + 128] = make_float2(av1.x, av1.x);  \
            *(float2*)&As2[S][lc + 1][2*lr + 128] = make_float2(av1.y, av1.y);  \
            *(float2*)&As2[S][lc + 2][2*lr + 128] = make_float2(av1.z, av1.z);  \
            *(float2*)&As2[S][lc + 3][2*lr + 128] = make_float2(av1.w, av1.w);  \
            Bs[S][lc + 0][lr]      = bv0.x; Bs[S][lc + 1][lr]      = bv0.y;     \
            Bs[S][lc + 2][lr]      = bv0.z; Bs[S][lc + 3][lr]      = bv0.w;     \
            Bs[S][lc + 0][lr + 64] = bv1.x; Bs[S][lc + 1][lr + 64] = bv1.y;     \
            Bs[S][lc + 2][lr + 64] = bv1.z; Bs[S][lc + 3][lr + 64] = bv1.w;     \
        } while (0)

    FILL_STAGE(0);
    __syncthreads();

    int st = 0;
    for (int k0 = 0; k0 < K; k0 += BK) {
        const bool more = (k0 + BK) < K;
        if (more) {  // prefetch next tile into registers
            av0 = *(const float4*)(Ap0 + k0 + BK);
            av1 = *(const float4*)(Ap1 + k0 + BK);
            bv0 = *(const float4*)(Bp0 + k0 + BK);
            bv1 = *(const float4*)(Bp1 + k0 + BK);
        }

        #pragma unroll
        for (int k = 0; k < BK; k++) {
            // A broadcast pairs: rows ty*8..ty*8+7 duplicated, 16 contiguous words
            const ulonglong2* apv = (const ulonglong2*)&As2[st][k][ty * 16];
            ulonglong2 aq0 = apv[0], aq1 = apv[1], aq2 = apv[2], aq3 = apv[3];
            ull ap[8] = { aq0.x, aq0.y, aq1.x, aq1.y, aq2.x, aq2.y, aq3.x, aq3.y };
            // B col pairs: 8 contiguous cols at tx*8
            const ulonglong2* bpv = (const ulonglong2*)&Bs[st][k][tx * 8];
            ulonglong2 bq0 = bpv[0], bq1 = bpv[1];
            ull bp[4] = { bq0.x, bq0.y, bq1.x, bq1.y };
            #pragma unroll
            for (int r = 0; r < 8; r++)
                #pragma unroll
                for (int c = 0; c < 4; c++) fma2(acc[r][c], ap[r], bp[c]);
        }

        if (more) FILL_STAGE(st ^ 1);
        __syncthreads();
        st ^= 1;
    }
    #undef FILL_STAGE

    // epilogue: unpack col pairs, add bias, optional silu, vector stores
    const int col0 = bn + tx * 8;
    float bb[8];
    #pragma unroll
    for (int c = 0; c < 8; c++) bb[c] = bias ? bias[col0 + c] : 0.f;

    #pragma unroll
    for (int r = 0; r < 8; r++) {
        float o[8];
        #pragma unroll
        for (int c = 0; c < 4; c++) {
            float2 v = upk2(acc[r][c]);
            o[2*c]   = v.x + bb[2*c];
            o[2*c+1] = v.y + bb[2*c+1];
        }
        if (act) {
            #pragma unroll
            for (int c = 0; c < 8; c++) o[c] = o[c] * (1.f / (1.f + __expf(-o[c])));
        }
        float* rp = &C[(size_t)(bm + ty * 8 + r) * ldc + col0];
        *(float4*)(rp)     = make_float4(o[0], o[1], o[2], o[3]);
        *(float4*)(rp + 4) = make_float4(o[4], o[5], o[6], o[7]);
    }
}

// ---------------- top-k (warp per token, registers only) ----------------
__device__ __forceinline__ unsigned ford(float v) {
    unsigned u = __float_as_uint(v);
    return (u & 0x80000000u) ? ~u : (u | 0x80000000u);
}
__device__ __forceinline__ float funord(unsigned k) {
    unsigned u = (k & 0x80000000u) ? (k ^ 0x80000000u) : ~k;
    return __uint_as_float(u);
}
__device__ __forceinline__ ull mkkey(float v, int idx) {
    return ((ull)ford(v) << 32) | (unsigned)(0xFFFFFFFFu - (unsigned)idx);
}

// stage 1/2: top-32 of 512; idx = j*32 + lane (owner = idx&31, slot = idx>>5)
__device__ __forceinline__ void select32_512(ull* kk, int lane, float &ov, int &oi) {
    for (int it = 0; it < PTOPK; ++it) {
        ull best = kk[0];
        #pragma unroll
        for (int j = 1; j < 16; j++) if (kk[j] > best) best = kk[j];
        #pragma unroll
        for (int o = 16; o > 0; o >>= 1) {
            ull t = __shfl_xor_sync(0xFFFFFFFFu, best, o);
            if (t > best) best = t;
        }
        int idx = (int)(0xFFFFFFFFu - (unsigned)best);
        if (lane == it) { ov = funord((unsigned)(best >> 32)); oi = idx; }
        int owner = idx & 31;
        int slot  = idx >> 5;
        if (lane == owner) {
            #pragma unroll
            for (int j = 0; j < 16; j++) if (j == slot) kk[j] = 0ull;
        }
    }
}

__global__ void topk_kernel() {
    const int gw   = (blockIdx.x * blockDim.x + threadIdx.x) >> 5;  // token
    const int lane = threadIdx.x & 31;
    const float* s1 = g_s1 + (size_t)gw * NKEYS;
    const float* s2 = g_s2 + (size_t)gw * NKEYS;

    float s1v = 0.f, s2v = 0.f, selv = 0.f;
    int   s1i = 0,   s2i = 0,   selp = 0;

    {
        ull kk[16];
        #pragma unroll
        for (int j = 0; j < 16; j++) { int idx = j * 32 + lane; kk[j] = mkkey(s1[idx], idx); }
        select32_512(kk, lane, s1v, s1i);
    }
    {
        ull kk[16];
        #pragma unroll
        for (int j = 0; j < 16; j++) { int idx = j * 32 + lane; kk[j] = mkkey(s2[idx], idx); }
        select32_512(kk, lane, s2v, s2i);
    }

    // Stage 3: top-32 of the 32x32 sum grid via sorted-merge pointer walk.
    // s1v (lane = rank i) and s2v (lane = rank j) are rank-sorted descending
    // with exact jax tie-breaking; each lane's candidates s1v + s2v[p]
    // (position lane*32+p) are sorted. Warp float-max + ballot; lowest set
    // lane = lowest position = jax tie-break.
    {
        int p = 0;
        float v = s1v + __shfl_sync(0xFFFFFFFFu, s2v, 0);
        for (int it = 0; it < PTOPK; ++it) {
            float bv = v;
            #pragma unroll
            for (int o = 16; o > 0; o >>= 1)
                bv = fmaxf(bv, __shfl_xor_sync(0xFFFFFFFFu, bv, o));
            unsigned m = __ballot_sync(0xFFFFFFFFu, v == bv);
            int wl = __ffs(m) - 1;
            int wp = __shfl_sync(0xFFFFFFFFu, p, wl);
            if (lane == it) { selv = bv; selp = wl * 32 + wp; }
            bool won = (lane == wl);
            p += won;
            float ns2 = __shfl_sync(0xFFFFFFFFu, s2v, p < 32 ? p : 31);
            if (won) v = (p < 32) ? (s1v + ns2) : -3.4e38f;
        }
    }

    // softmax(scores / sqrt(1024)); lane 0 holds the max
    float mx = __shfl_sync(0xFFFFFFFFu, selv, 0);
    float e = __expf((selv - mx) * 0.03125f);
    float s = e;
    #pragma unroll
    for (int o = 16; o > 0; o >>= 1) s += __shfl_xor_sync(0xFFFFFFFFu, s, o);
    float w = e / s;

    int i1 = __shfl_sync(0xFFFFFFFFu, s1i, selp >> 5);
    int i2 = __shfl_sync(0xFFFFFFFFu, s2i, selp & 31);
    g_tidx[gw * PTOPK + lane] = i1 * NKEYS + i2;
    g_tw  [gw * PTOPK + lane] = w;
}

// ---------------- gather + weighted sum + gate (HBM-bound, ~80% of spec) ----------
__global__ void gather_kernel(const float* __restrict__ values) {
    const int token = blockIdx.x;
    const int tid   = threadIdx.x;
    __shared__ int   sidx[PTOPK];
    __shared__ float sw  [PTOPK];
    if (tid < PTOPK) {
        sidx[tid] = g_tidx[token * PTOPK + tid];
        sw  [tid] = g_tw  [token * PTOPK + tid];
    }
    __syncthreads();

    float4 acc = make_float4(0.f, 0.f, 0.f, 0.f);
    #pragma unroll 8
    for (int k = 0; k < PTOPK; k++) {
        const float4* row = (const float4*)(values + (size_t)sidx[k] * PDIM);
        float4 v = __ldg(row + tid);
        float wk = sw[k];
        acc.x += wk * v.x; acc.y += wk * v.y; acc.z += wk * v.z; acc.w += wk * v.w;
    }
    float4 g = ((const float4*)(g_gate + (size_t)token * PDIM))[tid];
    acc.x *= g.x; acc.y *= g.y; acc.z *= g.z; acc.w *= g.w;
    ((float4*)(g_mid + (size_t)token * PDIM))[tid] = acc;
}

// ---------------- launch ----------------
extern "C" void kernel_launch(void* const* d_in, const int* in_sizes, int n_in,
                              void* d_out, int out_size) {
    (void)in_sizes; (void)n_in; (void)out_size;
    const float* x      = (const float*)d_in[0];
    const float* ke1    = (const float*)d_in[1];
    const float* ke2    = (const float*)d_in[2];
    const float* values = (const float*)d_in[3];
    const float* Wq     = (const float*)d_in[4];
    const float* bq     = (const float*)d_in[5];
    const float* Wg     = (const float*)d_in[6];
    const float* bg     = (const float*)d_in[7];
    const float* Wo     = (const float*)d_in[8];
    const float* bo     = (const float*)d_in[9];
    float* out = (float*)d_out;

    float *q, *gt, *s1, *s2, *mid;
    cudaGetSymbolAddress((void**)&q,   g_query);
    cudaGetSymbolAddress((void**)&gt,  g_gate);
    cudaGetSymbolAddress((void**)&s1,  g_s1);
    cudaGetSymbolAddress((void**)&s2,  g_s2);
    cudaGetSymbolAddress((void**)&mid, g_mid);

    dim3 blk(256);
    // fused: query = x@Wq^T + bq  ||  gate = silu(x@Wg^T + bg)   (grid 512)
    gemm_tn<<<dim3(16, TOKENS / BM), blk>>>(x, Wq, Wg, bq, bg, q, gt,
                                            PDIM, PDIM, PDIM, PDIM,
                                            /*nx0=*/8, /*aoff1=*/0, 0, 1);
    // fused: s1 = q[:, :512]@ke1^T  ||  s2 = q[:, 512:]@ke2^T    (grid 256)
    gemm_tn<<<dim3(8, TOKENS / BM), blk>>>(q, ke1, ke2, nullptr, nullptr, s1, s2,
                                           PHALF, PDIM, PHALF, NKEYS,
                                           /*nx0=*/4, /*aoff1=*/PHALF, 0, 0);
    // two-stage top-k + softmax weights (warp per token)
    topk_kernel<<<TOKENS / 8, 256>>>();
    // weighted gather of values rows, times gate
    gather_kernel<<<TOKENS, 256>>>(values);
    // out = mid@Wo^T + bo                                        (grid 256)
    gemm_tn<<<dim3(8, TOKENS / BM), blk>>>(mid, Wo, Wo, bo, bo, out, out,
                                           PDIM, PDIM, PDIM, PDIM,
                                           /*nx0=*/8, /*aoff1=*/0, 0, 0);
}

// round 13
// speedup vs baseline: 2.8940x; 1.4156x over previous
#include <cuda_runtime.h>
#include <cuda_bf16.h>
#include <cstdint>

typedef unsigned long long ull;
typedef __nv_bfloat16 bf16;

#define TOKENS 4096
#define PDIM   1024
#define PHALF  512
#define NKEYS  512
#define PTOPK  32

// ---------------- scratch (static device arrays; no cudaMalloc) ----------------
__device__ float g_query[TOKENS * PDIM];
__device__ float g_gate [TOKENS * PDIM];
__device__ float g_s1   [TOKENS * NKEYS];
__device__ float g_s2   [TOKENS * NKEYS];
__device__ float g_mid  [TOKENS * PDIM];
__device__ int   g_tidx [TOKENS * PTOPK];
__device__ float g_tw   [TOKENS * PTOPK];

// bf16-split operand buffers (K concatenated by slot count)
__device__ bf16 g_x6 [(size_t)TOKENS * PDIM  * 6];   // x, 3-term A-mode
__device__ bf16 g_x3 [(size_t)TOKENS * PDIM  * 3];   // x, 2-term A-mode
__device__ bf16 g_m3 [(size_t)TOKENS * PDIM  * 3];   // mid, 2-term A-mode
__device__ bf16 g_q6a[(size_t)TOKENS * PHALF * 6];
__device__ bf16 g_q6b[(size_t)TOKENS * PHALF * 6];
__device__ bf16 g_wq6[(size_t)PDIM * PDIM * 6];
__device__ bf16 g_wg3[(size_t)PDIM * PDIM * 3];
__device__ bf16 g_wo3[(size_t)PDIM * PDIM * 3];
__device__ bf16 g_k16[(size_t)NKEYS * PHALF * 6];
__device__ bf16 g_k26[(size_t)NKEYS * PHALF * 6];

// ---------------- helpers ----------------
__device__ __forceinline__ uint32_t smem_u32(const void* p) {
    uint32_t a;
    asm("{ .reg .u64 t; cvta.to.shared.u64 t, %1; cvt.u32.u64 %0, t; }" : "=r"(a) : "l"(p));
    return a;
}
#define LDSM4(r0, r1, r2, r3, addr)                                             \
    asm volatile("ldmatrix.sync.aligned.m8n8.x4.shared.b16 {%0,%1,%2,%3}, [%4];" \
                 : "=r"(r0), "=r"(r1), "=r"(r2), "=r"(r3) : "r"(addr))
#define MMA16816(c, a0, a1, a2, a3, b0, b1)                                     \
    asm volatile("mma.sync.aligned.m16n8k16.row.col.f32.bf16.bf16.f32 "         \
                 "{%0,%1,%2,%3}, {%4,%5,%6,%7}, {%8,%9}, {%0,%1,%2,%3};"        \
                 : "+f"((c)[0]), "+f"((c)[1]), "+f"((c)[2]), "+f"((c)[3])        \
                 : "r"(a0), "r"(a1), "r"(a2), "r"(a3), "r"(b0), "r"(b1))

// ---------------- split kernels: fp32 -> NS bf16 parts, K-concatenated ----------------
// a = h + m + l (exact bf16 residual splits). Slot orders:
//  NS=6: A{h,h,m,h,l,m} B{h,m,h,l,h,m} -> hh,hm,mh,hl,lh,mm (err ~2^-27)
//  NS=3: A{h,h,m}       B{h,m,h}       -> hh,hm,mh          (err ~2^-18)
template <int NS, int MODE>
__global__ void splitN(const float* __restrict__ X, bf16* __restrict__ Y,
                       int total, int Kin, int ldx)
{
    int idx = blockIdx.x * blockDim.x + threadIdx.x;
    if (idx >= total) return;
    int r = idx / Kin, k = idx - r * Kin;
    float a = X[(size_t)r * ldx + k];
    bf16 hb = __float2bfloat16(a);
    float r1 = a - __bfloat162float(hb);
    bf16 mb = __float2bfloat16(r1);
    float r2 = r1 - __bfloat162float(mb);
    bf16 lb = __float2bfloat16(r2);
    bf16 parts[3] = { hb, mb, lb };
    const int PA6[6] = {0,0,1,0,2,1};
    const int PB6[6] = {0,1,0,2,0,1};
    const int PA3[3] = {0,0,1};
    const int PB3[3] = {0,1,0};
    size_t base = (size_t)r * (NS * Kin) + k;
    #pragma unroll
    for (int p = 0; p < NS; p++) {
        int sel = (NS == 6) ? (MODE ? PB6[p] : PA6[p]) : (MODE ? PB3[p] : PA3[p]);
        Y[base + (size_t)p * Kin] = parts[sel];
    }
}

// ---------------- HMMA bf16 TN GEMM: C[M,N] = A[M,K]*B[N,K]^T (+bias, silu) ----------
// BM=BN=128, BK=32, 8 warps (4m x 2n), warp tile 32x64, m16n8k16 fragments.
// smem rows padded to 40 halves (80B) -> conflict-free ldmatrix. Double buffered.
// Grid.x section split: blocks [0,nx0) -> {A0,B0,bias0,C0,K0,act0}; rest -> set 1.
#define STG 10240    // bytes per A (or B) stage: 128 rows * 80B
#define BOFF 20480   // B region offset

__global__ __launch_bounds__(256, 2)
void gemm_mma(const bf16* __restrict__ A0, const bf16* __restrict__ A1,
              const bf16* __restrict__ B0, const bf16* __restrict__ B1,
              const float* __restrict__ bias0, const float* __restrict__ bias1,
              float* __restrict__ C0, float* __restrict__ C1,
              int ldc0, int ldc1, int K0, int K1, int nx0, int act0, int act1)
{
    extern __shared__ char smem[];
    const uint32_t sb = smem_u32(smem);

    const bool sec = (int)blockIdx.x >= nx0;
    const bf16* A     = sec ? A1 : A0;
    const bf16* B     = sec ? B1 : B0;
    const float* bias = sec ? bias1 : bias0;
    float* C          = sec ? C1 : C0;
    const int ldc     = sec ? ldc1 : ldc0;
    const int K       = sec ? K1 : K0;
    const int act     = sec ? act1 : act0;
    const int bn      = (sec ? (int)blockIdx.x - nx0 : (int)blockIdx.x) * 128;
    const int bm      = blockIdx.y * 128;

    const int tid = threadIdx.x, wid = tid >> 5, lane = tid & 31;
    const int wm = wid & 3, wn = wid >> 2;          // warp tile: rows wm*32, cols wn*64

    // global load mapping: thread -> rows (tid>>2, +64), 8-half chunk q=tid&3
    const int lr = tid >> 2, lq = tid & 3;
    const bf16* Ag = A + (size_t)(bm + lr) * K + lq * 8;
    const bf16* Bg = B + (size_t)(bn + lr) * K + lq * 8;
    char* sA0 = smem + (lr * 40 + lq * 8) * 2;          // + stage*STG; row+64 at +5120
    char* sB0 = smem + BOFF + (lr * 40 + lq * 8) * 2;

    // ldmatrix addresses (stage 0)
    const int arow = wm * 32 + (lane & 15);
    const int acol = (lane >> 4) * 8;
    uint32_t aAd[2][2];
    #pragma unroll
    for (int mt = 0; mt < 2; mt++)
        #pragma unroll
        for (int ks = 0; ks < 2; ks++)
            aAd[mt][ks] = sb + ((arow + mt * 16) * 40 + ks * 16 + acol) * 2;
    const int brow = wn * 64 + (lane & 7) + ((lane >> 4) & 1) * 8;
    const int bcol = ((lane >> 3) & 1) * 8;
    uint32_t bAd[2];
    #pragma unroll
    for (int ks = 0; ks < 2; ks++)
        bAd[ks] = sb + BOFF + (brow * 40 + ks * 16 + bcol) * 2;

    float acc[2][8][4];
    #pragma unroll
    for (int mt = 0; mt < 2; mt++)
        #pragma unroll
        for (int nt = 0; nt < 8; nt++)
            #pragma unroll
            for (int c = 0; c < 4; c++) acc[mt][nt][c] = 0.f;

    uint4 ra0 = *(const uint4*)Ag;
    uint4 ra1 = *(const uint4*)(Ag + (size_t)64 * K);
    uint4 rb0 = *(const uint4*)Bg;
    uint4 rb1 = *(const uint4*)(Bg + (size_t)64 * K);
    *(uint4*)sA0 = ra0; *(uint4*)(sA0 + 5120) = ra1;
    *(uint4*)sB0 = rb0; *(uint4*)(sB0 + 5120) = rb1;
    __syncthreads();

    const int NT = K >> 5;
    int s = 0;
    for (int i = 0; i < NT; i++) {
        const bool more = (i + 1) < NT;
        if (more) {
            const int k0 = (i + 1) * 32;
            ra0 = *(const uint4*)(Ag + k0);
            ra1 = *(const uint4*)(Ag + (size_t)64 * K + k0);
            rb0 = *(const uint4*)(Bg + k0);
            rb1 = *(const uint4*)(Bg + (size_t)64 * K + k0);
        }
        const uint32_t so = s * STG;
        #pragma unroll
        for (int ks = 0; ks < 2; ks++) {
            uint32_t a0, a1, a2, a3, a4, a5, a6, a7;
            LDSM4(a0, a1, a2, a3, aAd[0][ks] + so);
            LDSM4(a4, a5, a6, a7, aAd[1][ks] + so);
            #pragma unroll
            for (int p = 0; p < 4; p++) {
                uint32_t b0, b1, b2, b3;
                LDSM4(b0, b1, b2, b3, bAd[ks] + so + p * 1280);
                MMA16816(acc[0][2*p],   a0, a1, a2, a3, b0, b1);
                MMA16816(acc[1][2*p],   a4, a5, a6, a7, b0, b1);
                MMA16816(acc[0][2*p+1], a0, a1, a2, a3, b2, b3);
                MMA16816(acc[1][2*p+1], a4, a5, a6, a7, b2, b3);
            }
        }
        if (more) {
            char* dA = sA0 + (s ^ 1) * STG;
            char* dB = sB0 + (s ^ 1) * STG;
            *(uint4*)dA = ra0; *(uint4*)(dA + 5120) = ra1;
            *(uint4*)dB = rb0; *(uint4*)(dB + 5120) = rb1;
        }
        __syncthreads();
        s ^= 1;
    }

    // epilogue
    const int colb = bn + wn * 64 + (lane & 3) * 2;
    #pragma unroll
    for (int mt = 0; mt < 2; mt++) {
        const int r0 = bm + wm * 32 + mt * 16 + (lane >> 2);
        #pragma unroll
        for (int h = 0; h < 2; h++) {
            const int row = r0 + h * 8;
            #pragma unroll
            for (int nt = 0; nt < 8; nt++) {
                const int col = colb + nt * 8;
                float v0 = acc[mt][nt][h * 2 + 0];
                float v1 = acc[mt][nt][h * 2 + 1];
                if (bias) { v0 += bias[col]; v1 += bias[col + 1]; }
                if (act) {
                    v0 *= 1.f / (1.f + __expf(-v0));
                    v1 *= 1.f / (1.f + __expf(-v1));
                }
                *(float2*)&C[(size_t)row * ldc + col] = make_float2(v0, v1);
            }
        }
    }
}

// ---------------- top-k (warp per token, registers only) ----------------
__device__ __forceinline__ unsigned ford(float v) {
    unsigned u = __float_as_uint(v);
    return (u & 0x80000000u) ? ~u : (u | 0x80000000u);
}
__device__ __forceinline__ float funord(unsigned k) {
    unsigned u = (k & 0x80000000u) ? (k ^ 0x80000000u) : ~k;
    return __uint_as_float(u);
}
__device__ __forceinline__ ull mkkey(float v, int idx) {
    return ((ull)ford(v) << 32) | (unsigned)(0xFFFFFFFFu - (unsigned)idx);
}

__device__ __forceinline__ void select32_512(ull* kk, int lane, float &ov, int &oi) {
    for (int it = 0; it < PTOPK; ++it) {
        ull best = kk[0];
        #pragma unroll
        for (int j = 1; j < 16; j++) if (kk[j] > best) best = kk[j];
        #pragma unroll
        for (int o = 16; o > 0; o >>= 1) {
            ull t = __shfl_xor_sync(0xFFFFFFFFu, best, o);
            if (t > best) best = t;
        }
        int idx = (int)(0xFFFFFFFFu - (unsigned)best);
        if (lane == it) { ov = funord((unsigned)(best >> 32)); oi = idx; }
        int owner = idx & 31;
        int slot  = idx >> 5;
        if (lane == owner) {
            #pragma unroll
            for (int j = 0; j < 16; j++) if (j == slot) kk[j] = 0ull;
        }
    }
}

__global__ void topk_kernel() {
    const int gw   = (blockIdx.x * blockDim.x + threadIdx.x) >> 5;
    const int lane = threadIdx.x & 31;
    const float* s1 = g_s1 + (size_t)gw * NKEYS;
    const float* s2 = g_s2 + (size_t)gw * NKEYS;

    float s1v = 0.f, s2v = 0.f, selv = 0.f;
    int   s1i = 0,   s2i = 0,   selp = 0;

    {
        ull kk[16];
        #pragma unroll
        for (int j = 0; j < 16; j++) { int idx = j * 32 + lane; kk[j] = mkkey(s1[idx], idx); }
        select32_512(kk, lane, s1v, s1i);
    }
    {
        ull kk[16];
        #pragma unroll
        for (int j = 0; j < 16; j++) { int idx = j * 32 + lane; kk[j] = mkkey(s2[idx], idx); }
        select32_512(kk, lane, s2v, s2i);
    }

    // Stage 3: sorted-merge pointer walk over the 32x32 sum grid.
    {
        int p = 0;
        float v = s1v + __shfl_sync(0xFFFFFFFFu, s2v, 0);
        for (int it = 0; it < PTOPK; ++it) {
            float bv = v;
            #pragma unroll
            for (int o = 16; o > 0; o >>= 1)
                bv = fmaxf(bv, __shfl_xor_sync(0xFFFFFFFFu, bv, o));
            unsigned m = __ballot_sync(0xFFFFFFFFu, v == bv);
            int wl = __ffs(m) - 1;
            int wp = __shfl_sync(0xFFFFFFFFu, p, wl);
            if (lane == it) { selv = bv; selp = wl * 32 + wp; }
            bool won = (lane == wl);
            p += won;
            float ns2 = __shfl_sync(0xFFFFFFFFu, s2v, p < 32 ? p : 31);
            if (won) v = (p < 32) ? (s1v + ns2) : -3.4e38f;
        }
    }

    float mx = __shfl_sync(0xFFFFFFFFu, selv, 0);
    float e = __expf((selv - mx) * 0.03125f);
    float s = e;
    #pragma unroll
    for (int o = 16; o > 0; o >>= 1) s += __shfl_xor_sync(0xFFFFFFFFu, s, o);
    float w = e / s;

    int i1 = __shfl_sync(0xFFFFFFFFu, s1i, selp >> 5);
    int i2 = __shfl_sync(0xFFFFFFFFu, s2i, selp & 31);
    g_tidx[gw * PTOPK + lane] = i1 * NKEYS + i2;
    g_tw  [gw * PTOPK + lane] = w;
}

// ---------------- gather + weighted sum + gate (HBM-bound, ~80% of spec) ----------
__global__ void gather_kernel(const float* __restrict__ values) {
    const int token = blockIdx.x;
    const int tid   = threadIdx.x;
    __shared__ int   sidx[PTOPK];
    __shared__ float sw  [PTOPK];
    if (tid < PTOPK) {
        sidx[tid] = g_tidx[token * PTOPK + tid];
        sw  [tid] = g_tw  [token * PTOPK + tid];
    }
    __syncthreads();

    float4 acc = make_float4(0.f, 0.f, 0.f, 0.f);
    #pragma unroll 8
    for (int k = 0; k < PTOPK; k++) {
        const float4* rowp = (const float4*)(values + (size_t)sidx[k] * PDIM);
        float4 v = __ldg(rowp + tid);
        float wk = sw[k];
        acc.x += wk * v.x; acc.y += wk * v.y; acc.z += wk * v.z; acc.w += wk * v.w;
    }
    float4 g = ((const float4*)(g_gate + (size_t)token * PDIM))[tid];
    acc.x *= g.x; acc.y *= g.y; acc.z *= g.z; acc.w *= g.w;
    ((float4*)(g_mid + (size_t)token * PDIM))[tid] = acc;
}

// ---------------- launch ----------------
extern "C" void kernel_launch(void* const* d_in, const int* in_sizes, int n_in,
                              void* d_out, int out_size) {
    (void)in_sizes; (void)n_in; (void)out_size;
    const float* x      = (const float*)d_in[0];
    const float* ke1    = (const float*)d_in[1];
    const float* ke2    = (const float*)d_in[2];
    const float* values = (const float*)d_in[3];
    const float* Wq     = (const float*)d_in[4];
    const float* bq     = (const float*)d_in[5];
    const float* Wg     = (const float*)d_in[6];
    const float* bg     = (const float*)d_in[7];
    const float* Wo     = (const float*)d_in[8];
    const float* bo     = (const float*)d_in[9];
    float* out = (float*)d_out;

    float *q, *gt, *s1, *s2, *mid;
    bf16 *x6, *x3, *m3, *q6a, *q6b, *wq6, *wg3, *wo3, *k16, *k26;
    cudaGetSymbolAddress((void**)&q,   g_query);
    cudaGetSymbolAddress((void**)&gt,  g_gate);
    cudaGetSymbolAddress((void**)&s1,  g_s1);
    cudaGetSymbolAddress((void**)&s2,  g_s2);
    cudaGetSymbolAddress((void**)&mid, g_mid);
    cudaGetSymbolAddress((void**)&x6,  g_x6);
    cudaGetSymbolAddress((void**)&x3,  g_x3);
    cudaGetSymbolAddress((void**)&m3,  g_m3);
    cudaGetSymbolAddress((void**)&q6a, g_q6a);
    cudaGetSymbolAddress((void**)&q6b, g_q6b);
    cudaGetSymbolAddress((void**)&wq6, g_wq6);
    cudaGetSymbolAddress((void**)&wg3, g_wg3);
    cudaGetSymbolAddress((void**)&wo3, g_wo3);
    cudaGetSymbolAddress((void**)&k16, g_k16);
    cudaGetSymbolAddress((void**)&k26, g_k26);

    const int T = 256;
    // operand splits
    splitN<6,1><<<(PDIM * PDIM + T - 1) / T, T>>>(Wq,  wq6, PDIM * PDIM, PDIM, PDIM);
    splitN<3,1><<<(PDIM * PDIM + T - 1) / T, T>>>(Wg,  wg3, PDIM * PDIM, PDIM, PDIM);
    splitN<3,1><<<(PDIM * PDIM + T - 1) / T, T>>>(Wo,  wo3, PDIM * PDIM, PDIM, PDIM);
    splitN<6,1><<<(NKEYS * PHALF + T - 1) / T, T>>>(ke1, k16, NKEYS * PHALF, PHALF, PHALF);
    splitN<6,1><<<(NKEYS * PHALF + T - 1) / T, T>>>(ke2, k26, NKEYS * PHALF, PHALF, PHALF);
    splitN<6,0><<<(TOKENS * PDIM + T - 1) / T, T>>>(x, x6, TOKENS * PDIM, PDIM, PDIM);
    splitN<3,0><<<(TOKENS * PDIM + T - 1) / T, T>>>(x, x3, TOKENS * PDIM, PDIM, PDIM);

    // G1: q = x@Wq^T + bq (6-slot) || gate = silu(x@Wg^T + bg) (3-slot)
    gemm_mma<<<dim3(16, TOKENS / 128), T, 40960>>>(
        x6, x3, wq6, wg3, bq, bg, q, gt, PDIM, PDIM,
        PDIM * 6, PDIM * 3, /*nx0=*/8, 0, 1);

    // split q halves (A-mode, 6-slot)
    splitN<6,0><<<(TOKENS * PHALF + T - 1) / T, T>>>(q,         q6a, TOKENS * PHALF, PHALF, PDIM);
    splitN<6,0><<<(TOKENS * PHALF + T - 1) / T, T>>>(q + PHALF, q6b, TOKENS * PHALF, PHALF, PDIM);

    // G2: s1 = q1@ke1^T || s2 = q2@ke2^T (6-slot, K=3072)
    gemm_mma<<<dim3(8, TOKENS / 128), T, 40960>>>(
        q6a, q6b, k16, k26, nullptr, nullptr, s1, s2, NKEYS, NKEYS,
        PHALF * 6, PHALF * 6, /*nx0=*/4, 0, 0);

    topk_kernel<<<TOKENS / 8, 256>>>();
    gather_kernel<<<TOKENS, 256>>>(values);

    // G3: out = mid@Wo^T + bo (3-slot)
    splitN<3,0><<<(TOKENS * PDIM + T - 1) / T, T>>>(mid, m3, TOKENS * PDIM, PDIM, PDIM);
    gemm_mma<<<dim3(8, TOKENS / 128), T, 40960>>>(
        m3, m3, wo3, wo3, bo, bo, out, out, PDIM, PDIM,
        PDIM * 3, PDIM * 3, /*nx0=*/8, 0, 0);
}

// round 15
// speedup vs baseline: 3.7088x; 1.2816x over previous
#include <cuda_runtime.h>
#include <cuda_bf16.h>
#include <cstdint>

typedef unsigned long long ull;
typedef __nv_bfloat16 bf16;

#define TOKENS 4096
#define PDIM   1024
#define PHALF  512
#define NKEYS  512
#define PTOPK  32

// ---------------- scratch (static device arrays; no cudaMalloc) ----------------
__device__ float g_query[TOKENS * PDIM];
__device__ float g_gate [TOKENS * PDIM];
__device__ float g_s1   [TOKENS * NKEYS];
__device__ float g_s2   [TOKENS * NKEYS];
__device__ float g_mid  [TOKENS * PDIM];
__device__ int   g_tidx [TOKENS * PTOPK];
__device__ float g_tw   [TOKENS * PTOPK];

// bf16-split operand buffers (K concatenated by slot count)
__device__ bf16 g_x6 [(size_t)TOKENS * PDIM  * 6];
__device__ bf16 g_x3 [(size_t)TOKENS * PDIM  * 3];
__device__ bf16 g_m3 [(size_t)TOKENS * PDIM  * 3];
__device__ bf16 g_q6a[(size_t)TOKENS * PHALF * 6];
__device__ bf16 g_q6b[(size_t)TOKENS * PHALF * 6];
__device__ bf16 g_wq6[(size_t)PDIM * PDIM * 6];
__device__ bf16 g_wg3[(size_t)PDIM * PDIM * 3];
__device__ bf16 g_wo3[(size_t)PDIM * PDIM * 3];
__device__ bf16 g_k16[(size_t)NKEYS * PHALF * 6];
__device__ bf16 g_k26[(size_t)NKEYS * PHALF * 6];

// ---------------- helpers ----------------
__device__ __forceinline__ uint32_t smem_u32(const void* p) {
    uint32_t a;
    asm("{ .reg .u64 t; cvta.to.shared.u64 t, %1; cvt.u32.u64 %0, t; }" : "=r"(a) : "l"(p));
    return a;
}
#define LDSM4(r0, r1, r2, r3, addr)                                             \
    asm volatile("ldmatrix.sync.aligned.m8n8.x4.shared.b16 {%0,%1,%2,%3}, [%4];" \
                 : "=r"(r0), "=r"(r1), "=r"(r2), "=r"(r3) : "r"(addr))
#define MMA16816(c, a0, a1, a2, a3, b0, b1)                                     \
    asm volatile("mma.sync.aligned.m16n8k16.row.col.f32.bf16.bf16.f32 "         \
                 "{%0,%1,%2,%3}, {%4,%5,%6,%7}, {%8,%9}, {%0,%1,%2,%3};"        \
                 : "+f"((c)[0]), "+f"((c)[1]), "+f"((c)[2]), "+f"((c)[3])        \
                 : "r"(a0), "r"(a1), "r"(a2), "r"(a3), "r"(b0), "r"(b1))
__device__ __forceinline__ void cpa16(uint32_t s, const bf16* g) {
    asm volatile("cp.async.cg.shared.global [%0], [%1], 16;" :: "r"(s), "l"(g) : "memory");
}
__device__ __forceinline__ void cpa_commit() {
    asm volatile("cp.async.commit_group;" ::: "memory");
}
__device__ __forceinline__ void cpa_wait1() {
    asm volatile("cp.async.wait_group 1;" ::: "memory");
}
// SW64-style swizzle: 16B-granule index (bits 4:5) ^= row bits 1:2 (bits 7:8).
__device__ __forceinline__ uint32_t swz(uint32_t off) { return off ^ ((off >> 3) & 0x30); }

// ---------------- split kernels: fp32 -> NS bf16 parts, K-concatenated, x4 vectorized ----
// a = h + m + l (exact bf16 residual splits). Slot orders:
//  NS=6: A{h,h,m,h,l,m} B{h,m,h,l,h,m} -> hh,hm,mh,hl,lh,mm (err ~2^-27)
//  NS=3: A{h,h,m}       B{h,m,h}       -> hh,hm,mh          (err ~2^-18)
template <int NS, int MODE>
__global__ void splitN(const float* __restrict__ X, bf16* __restrict__ Y,
                       int total4, int Kin, int ldx)
{
    int idx = blockIdx.x * blockDim.x + threadIdx.x;
    if (idx >= total4) return;
    const int Kin4 = Kin >> 2;
    int r = idx / Kin4, k4 = (idx - r * Kin4) << 2;
    float4 a4 = *(const float4*)&X[(size_t)r * ldx + k4];
    float av[4] = { a4.x, a4.y, a4.z, a4.w };
    bf16 P[3][4];
    #pragma unroll
    for (int j = 0; j < 4; j++) {
        float a = av[j];
        bf16 hb = __float2bfloat16(a);
        float r1 = a - __bfloat162float(hb);
        bf16 mb = __float2bfloat16(r1);
        float r2 = r1 - __bfloat162float(mb);
        P[0][j] = hb; P[1][j] = mb; P[2][j] = __float2bfloat16(r2);
    }
    const int PA6[6] = {0,0,1,0,2,1};
    const int PB6[6] = {0,1,0,2,0,1};
    const int PA3[3] = {0,0,1};
    const int PB3[3] = {0,1,0};
    size_t base = (size_t)r * (NS * Kin) + k4;
    #pragma unroll
    for (int p = 0; p < NS; p++) {
        int sel = (NS == 6) ? (MODE ? PB6[p] : PA6[p]) : (MODE ? PB3[p] : PA3[p]);
        *(uint2*)&Y[base + (size_t)p * Kin] = *(uint2*)P[sel];
    }
}

// ---------------- HMMA bf16 TN GEMM with cp.async 3-stage pipeline ----------------
// C[M,N] = A[M,K]*B[N,K]^T (+bias, silu). BM=BN=128, BK=32, 8 warps (4m x 2n),
// warp tile 32x64. smem: 64B rows + XOR swizzle -> conflict-free ldmatrix and
// cp.async stores. Per-stage [A:8192B][B:8192B], 3 stages = 49152B (48KB, no
// opt-in needed). One barrier per K-iter. Grid.x section split at nx0.
#define STG    16384
#define NSTG   3
#define SMEMSZ 49152

__global__ __launch_bounds__(256, 2)
void gemm_mma(const bf16* __restrict__ A0, const bf16* __restrict__ A1,
              const bf16* __restrict__ B0, const bf16* __restrict__ B1,
              const float* __restrict__ bias0, const float* __restrict__ bias1,
              float* __restrict__ C0, float* __restrict__ C1,
              int ldc0, int ldc1, int K0, int K1, int nx0, int act0, int act1)
{
    extern __shared__ char smem[];
    const uint32_t sb = smem_u32(smem);

    const bool sec = (int)blockIdx.x >= nx0;
    const bf16* A     = sec ? A1 : A0;
    const bf16* B     = sec ? B1 : B0;
    const float* bias = sec ? bias1 : bias0;
    float* C          = sec ? C1 : C0;
    const int ldc     = sec ? ldc1 : ldc0;
    const int K       = sec ? K1 : K0;
    const int act     = sec ? act1 : act0;
    const int bn      = (sec ? (int)blockIdx.x - nx0 : (int)blockIdx.x) * 128;
    const int bm      = blockIdx.y * 128;

    const int tid = threadIdx.x, wid = tid >> 5, lane = tid & 31;
    const int wm = wid & 3, wn = wid >> 2;

    // global->smem mapping: thread -> rows (tid>>2, +64), 16B granule lq=tid&3
    const int lr = tid >> 2, lq = tid & 3;
    const bf16* Ag = A + (size_t)(bm + lr) * K + lq * 8;
    const bf16* Bg = B + (size_t)(bn + lr) * K + lq * 8;
    const uint32_t wloc = swz(lr * 64 + lq * 16);   // rows+64 -> +4096 (swizzle-invariant)
    const uint32_t wA = sb + wloc;                  // + stage*STG
    const uint32_t wB = wA + 8192;

    // ldmatrix addresses (stage 0); stage adds STG, swizzle-invariant offsets
    const int arow = wm * 32 + (lane & 15);
    uint32_t aAd[2][2];
    #pragma unroll
    for (int mt = 0; mt < 2; mt++)
        #pragma unroll
        for (int ks = 0; ks < 2; ks++)
            aAd[mt][ks] = sb + swz((arow + mt * 16) * 64 + ks * 32 + (lane >> 4) * 16);
    const int brow = wn * 64 + (lane & 7) + ((lane >> 4) & 1) * 8;
    uint32_t bAd[2];
    #pragma unroll
    for (int ks = 0; ks < 2; ks++)
        bAd[ks] = sb + 8192 + swz(brow * 64 + ks * 32 + ((lane >> 3) & 1) * 16);

    float acc[2][8][4];
    #pragma unroll
    for (int mt = 0; mt < 2; mt++)
        #pragma unroll
        for (int nt = 0; nt < 8; nt++)
            #pragma unroll
            for (int c = 0; c < 4; c++) acc[mt][nt][c] = 0.f;

    const int NT = K >> 5;

    // prologue: fill stages 0..NSTG-2
    #pragma unroll
    for (int s = 0; s < NSTG - 1; s++) {
        const int k0 = s * 32;
        const uint32_t off = s * STG;
        cpa16(wA + off, Ag + k0);
        cpa16(wA + off + 4096, Ag + (size_t)64 * K + k0);
        cpa16(wB + off, Bg + k0);
        cpa16(wB + off + 4096, Bg + (size_t)64 * K + k0);
        cpa_commit();
    }

    int st = 0;
    for (int i = 0; i < NT; i++) {
        cpa_wait1();            // tile i's group complete (this thread)
        __syncthreads();        // all threads' tile-i data visible; prev compute done
        const int kn = i + NSTG - 1;
        if (kn < NT) {          // refill stage (st+NSTG-1)%NSTG with tile kn
            const int k0 = kn * 32;
            const int sn = st + NSTG - 1 - ((st + NSTG - 1 >= NSTG) ? NSTG : 0);
            const uint32_t off = sn * STG;
            cpa16(wA + off, Ag + k0);
            cpa16(wA + off + 4096, Ag + (size_t)64 * K + k0);
            cpa16(wB + off, Bg + k0);
            cpa16(wB + off + 4096, Bg + (size_t)64 * K + k0);
        }
        cpa_commit();           // uniform (empty in tail) keeps wait counting exact

        const uint32_t so = st * STG;
        #pragma unroll
        for (int ks = 0; ks < 2; ks++) {
            uint32_t a0, a1, a2, a3, a4, a5, a6, a7;
            LDSM4(a0, a1, a2, a3, aAd[0][ks] + so);
            LDSM4(a4, a5, a6, a7, aAd[1][ks] + so);
            #pragma unroll
            for (int p = 0; p < 4; p++) {
                uint32_t b0, b1, b2, b3;
                LDSM4(b0, b1, b2, b3, bAd[ks] + so + p * 1024);  // +16 rows per p
                MMA16816(acc[0][2*p],   a0, a1, a2, a3, b0, b1);
                MMA16816(acc[1][2*p],   a4, a5, a6, a7, b0, b1);
                MMA16816(acc[0][2*p+1], a0, a1, a2, a3, b2, b3);
                MMA16816(acc[1][2*p+1], a4, a5, a6, a7, b2, b3);
            }
        }
        st = (st + 1 == NSTG) ? 0 : st + 1;
    }

    // epilogue
    const int colb = bn + wn * 64 + (lane & 3) * 2;
    #pragma unroll
    for (int mt = 0; mt < 2; mt++) {
        const int r0 = bm + wm * 32 + mt * 16 + (lane >> 2);
        #pragma unroll
        for (int h = 0; h < 2; h++) {
            const int row = r0 + h * 8;
            #pragma unroll
            for (int nt = 0; nt < 8; nt++) {
                const int col = colb + nt * 8;
                float v0 = acc[mt][nt][h * 2 + 0];
                float v1 = acc[mt][nt][h * 2 + 1];
                if (bias) { v0 += bias[col]; v1 += bias[col + 1]; }
                if (act) {
                    v0 *= 1.f / (1.f + __expf(-v0));
                    v1 *= 1.f / (1.f + __expf(-v1));
                }
                *(float2*)&C[(size_t)row * ldc + col] = make_float2(v0, v1);
            }
        }
    }
}

// ---------------- top-k (warp per token, registers only) ----------------
__device__ __forceinline__ unsigned ford(float v) {
    unsigned u = __float_as_uint(v);
    return (u & 0x80000000u) ? ~u : (u | 0x80000000u);
}
__device__ __forceinline__ float funord(unsigned k) {
    unsigned u = (k & 0x80000000u) ? (k ^ 0x80000000u) : ~k;
    return __uint_as_float(u);
}
__device__ __forceinline__ ull mkkey(float v, int idx) {
    return ((ull)ford(v) << 32) | (unsigned)(0xFFFFFFFFu - (unsigned)idx);
}

__device__ __forceinline__ void select32_512(ull* kk, int lane, float &ov, int &oi) {
    for (int it = 0; it < PTOPK; ++it) {
        ull best = kk[0];
        #pragma unroll
        for (int j = 1; j < 16; j++) if (kk[j] > best) best = kk[j];
        #pragma unroll
        for (int o = 16; o > 0; o >>= 1) {
            ull t = __shfl_xor_sync(0xFFFFFFFFu, best, o);
            if (t > best) best = t;
        }
        int idx = (int)(0xFFFFFFFFu - (unsigned)best);
        if (lane == it) { ov = funord((unsigned)(best >> 32)); oi = idx; }
        int owner = idx & 31;
        int slot  = idx >> 5;
        if (lane == owner) {
            #pragma unroll
            for (int j = 0; j < 16; j++) if (j == slot) kk[j] = 0ull;
        }
    }
}

__global__ void topk_kernel() {
    const int gw   = (blockIdx.x * blockDim.x + threadIdx.x) >> 5;
    const int lane = threadIdx.x & 31;
    const float* s1 = g_s1 + (size_t)gw * NKEYS;
    const float* s2 = g_s2 + (size_t)gw * NKEYS;

    float s1v = 0.f, s2v = 0.f, selv = 0.f;
    int   s1i = 0,   s2i = 0,   selp = 0;

    {
        ull kk[16];
        #pragma unroll
        for (int j = 0; j < 16; j++) { int idx = j * 32 + lane; kk[j] = mkkey(s1[idx], idx); }
        select32_512(kk, lane, s1v, s1i);
    }
    {
        ull kk[16];
        #pragma unroll
        for (int j = 0; j < 16; j++) { int idx = j * 32 + lane; kk[j] = mkkey(s2[idx], idx); }
        select32_512(kk, lane, s2v, s2i);
    }

    // Stage 3: sorted-merge pointer walk over the 32x32 sum grid.
    {
        int p = 0;
        float v = s1v + __shfl_sync(0xFFFFFFFFu, s2v, 0);
        for (int it = 0; it < PTOPK; ++it) {
            float bv = v;
            #pragma unroll
            for (int o = 16; o > 0; o >>= 1)
                bv = fmaxf(bv, __shfl_xor_sync(0xFFFFFFFFu, bv, o));
            unsigned m = __ballot_sync(0xFFFFFFFFu, v == bv);
            int wl = __ffs(m) - 1;
            int wp = __shfl_sync(0xFFFFFFFFu, p, wl);
            if (lane == it) { selv = bv; selp = wl * 32 + wp; }
            bool won = (lane == wl);
            p += won;
            float ns2 = __shfl_sync(0xFFFFFFFFu, s2v, p < 32 ? p : 31);
            if (won) v = (p < 32) ? (s1v + ns2) : -3.4e38f;
        }
    }

    float mx = __shfl_sync(0xFFFFFFFFu, selv, 0);
    float e = __expf((selv - mx) * 0.03125f);
    float s = e;
    #pragma unroll
    for (int o = 16; o > 0; o >>= 1) s += __shfl_xor_sync(0xFFFFFFFFu, s, o);
    float w = e / s;

    int i1 = __shfl_sync(0xFFFFFFFFu, s1i, selp >> 5);
    int i2 = __shfl_sync(0xFFFFFFFFu, s2i, selp & 31);
    g_tidx[gw * PTOPK + lane] = i1 * NKEYS + i2;
    g_tw  [gw * PTOPK + lane] = w;
}

// ---------------- gather + weighted sum + gate (HBM-bound, ~80% of spec) ----------
__global__ void gather_kernel(const float* __restrict__ values) {
    const int token = blockIdx.x;
    const int tid   = threadIdx.x;
    __shared__ int   sidx[PTOPK];
    __shared__ float sw  [PTOPK];
    if (tid < PTOPK) {
        sidx[tid] = g_tidx[token * PTOPK + tid];
        sw  [tid] = g_tw  [token * PTOPK + tid];
    }
    __syncthreads();

    float4 acc = make_float4(0.f, 0.f, 0.f, 0.f);
    #pragma unroll 8
    for (int k = 0; k < PTOPK; k++) {
        const float4* rowp = (const float4*)(values + (size_t)sidx[k] * PDIM);
        float4 v = __ldg(rowp + tid);
        float wk = sw[k];
        acc.x += wk * v.x; acc.y += wk * v.y; acc.z += wk * v.z; acc.w += wk * v.w;
    }
    float4 g = ((const float4*)(g_gate + (size_t)token * PDIM))[tid];
    acc.x *= g.x; acc.y *= g.y; acc.z *= g.z; acc.w *= g.w;
    ((float4*)(g_mid + (size_t)token * PDIM))[tid] = acc;
}

// ---------------- launch ----------------
extern "C" void kernel_launch(void* const* d_in, const int* in_sizes, int n_in,
                              void* d_out, int out_size) {
    (void)in_sizes; (void)n_in; (void)out_size;
    const float* x      = (const float*)d_in[0];
    const float* ke1    = (const float*)d_in[1];
    const float* ke2    = (const float*)d_in[2];
    const float* values = (const float*)d_in[3];
    const float* Wq     = (const float*)d_in[4];
    const float* bq     = (const float*)d_in[5];
    const float* Wg     = (const float*)d_in[6];
    const float* bg     = (const float*)d_in[7];
    const float* Wo     = (const float*)d_in[8];
    const float* bo     = (const float*)d_in[9];
    float* out = (float*)d_out;

    float *q, *gt, *s1, *s2, *mid;
    bf16 *x6, *x3, *m3, *q6a, *q6b, *wq6, *wg3, *wo3, *k16, *k26;
    cudaGetSymbolAddress((void**)&q,   g_query);
    cudaGetSymbolAddress((void**)&gt,  g_gate);
    cudaGetSymbolAddress((void**)&s1,  g_s1);
    cudaGetSymbolAddress((void**)&s2,  g_s2);
    cudaGetSymbolAddress((void**)&mid, g_mid);
    cudaGetSymbolAddress((void**)&x6,  g_x6);
    cudaGetSymbolAddress((void**)&x3,  g_x3);
    cudaGetSymbolAddress((void**)&m3,  g_m3);
    cudaGetSymbolAddress((void**)&q6a, g_q6a);
    cudaGetSymbolAddress((void**)&q6b, g_q6b);
    cudaGetSymbolAddress((void**)&wq6, g_wq6);
    cudaGetSymbolAddress((void**)&wg3, g_wg3);
    cudaGetSymbolAddress((void**)&wo3, g_wo3);
    cudaGetSymbolAddress((void**)&k16, g_k16);
    cudaGetSymbolAddress((void**)&k26, g_k26);

    const int T = 256;
    // operand splits (x4 vectorized; counts are /4)
    splitN<6,1><<<(PDIM * PDIM / 4 + T - 1) / T, T>>>(Wq,  wq6, PDIM * PDIM / 4, PDIM, PDIM);
    splitN<3,1><<<(PDIM * PDIM / 4 + T - 1) / T, T>>>(Wg,  wg3, PDIM * PDIM / 4, PDIM, PDIM);
    splitN<3,1><<<(PDIM * PDIM / 4 + T - 1) / T, T>>>(Wo,  wo3, PDIM * PDIM / 4, PDIM, PDIM);
    splitN<6,1><<<(NKEYS * PHALF / 4 + T - 1) / T, T>>>(ke1, k16, NKEYS * PHALF / 4, PHALF, PHALF);
    splitN<6,1><<<(NKEYS * PHALF / 4 + T - 1) / T, T>>>(ke2, k26, NKEYS * PHALF / 4, PHALF, PHALF);
    splitN<6,0><<<(TOKENS * PDIM / 4 + T - 1) / T, T>>>(x, x6, TOKENS * PDIM / 4, PDIM, PDIM);
    splitN<3,0><<<(TOKENS * PDIM / 4 + T - 1) / T, T>>>(x, x3, TOKENS * PDIM / 4, PDIM, PDIM);

    // G1: q = x@Wq^T + bq (6-slot) || gate = silu(x@Wg^T + bg) (3-slot)
    gemm_mma<<<dim3(16, TOKENS / 128), T, SMEMSZ>>>(
        x6, x3, wq6, wg3, bq, bg, q, gt, PDIM, PDIM,
        PDIM * 6, PDIM * 3, /*nx0=*/8, 0, 1);

    // split q halves (A-mode, 6-slot)
    splitN<6,0><<<(TOKENS * PHALF / 4 + T - 1) / T, T>>>(q,         q6a, TOKENS * PHALF / 4, PHALF, PDIM);
    splitN<6,0><<<(TOKENS * PHALF / 4 + T - 1) / T, T>>>(q + PHALF, q6b, TOKENS * PHALF / 4, PHALF, PDIM);

    // G2: s1 = q1@ke1^T || s2 = q2@ke2^T (6-slot, K=3072)
    gemm_mma<<<dim3(8, TOKENS / 128), T, SMEMSZ>>>(
        q6a, q6b, k16, k26, nullptr, nullptr, s1, s2, NKEYS, NKEYS,
        PHALF * 6, PHALF * 6, /*nx0=*/4, 0, 0);

    topk_kernel<<<TOKENS / 8, 256>>>();
    gather_kernel<<<TOKENS, 256>>>(values);

    // G3: out = mid@Wo^T + bo (3-slot)
    splitN<3,0><<<(TOKENS * PDIM / 4 + T - 1) / T, T>>>(mid, m3, TOKENS * PDIM / 4, PDIM, PDIM);
    gemm_mma<<<dim3(8, TOKENS / 128), T, SMEMSZ>>>(
        m3, m3, wo3, wo3, bo, bo, out, out, PDIM, PDIM,
        PDIM * 3, PDIM * 3, /*nx0=*/8, 0, 0);
}